// round 3
// baseline (speedup 1.0000x reference)
#include <cuda_runtime.h>
#include <math.h>

// SinusoidalOscillator: out[b,n] = sin(S0[n]) where S0 is the inclusive f32 scan
// of padded x (x[0]=0, x[j]=f0+(env[j-1]*am)*f0) computed with jax
// lax.associative_scan's tree. Closed form used here (bit-identical to the tree
// recursion): S0[n] = left-assoc fold, coarsest->finest, of the tree nodes in the
// binary decomposition of count c=n+1. Tree nodes L_k are exact pairwise sums;
// warp butterflies reproduce them bitwise (f32 add is commutative).

#define NSAMP  65536
#define NCH    (NSAMP / 32)      // 2048 chunks of 32
#define BS     256
#define NW     (BS / 32)

// L5..L16 packed: LOFF(k) = 4096 - (NSAMP >> (k-1)); sizes 2048,1024,...,1
#define LOFF(k) (4096 - (NSAMP >> ((k) - 1)))

__global__ __launch_bounds__(BS)
void osc_kernel(const float* __restrict__ freq,
                const float* __restrict__ env,
                const float* __restrict__ moda,
                float* __restrict__ out)
{
    __shared__ float lev[4096];       // L5..L16 (4095 used)
    __shared__ float P[NCH + 1];      // coarse prefix per chunk, +1 for lane31 of last chunk

    const int row  = blockIdx.x;
    const int tid  = threadIdx.x;
    const int lane = tid & 31;
    const int wid  = tid >> 5;

    const float f0hz = __fadd_rn(20.0f, __fmul_rn(1980.0f, freq[row]));
    const float f0   = __fdiv_rn(__fmul_rn(f0hz, 6.28318530717958647692f), 48000.0f);
    const float am   = __fadd_rn(-1.0f, __fmul_rn(3.0f, moda[row]));

    const float* e = env + (size_t)row * NSAMP;
    float*       o = out + (size_t)row * NSAMP;

    // ---- Phase A: L5[b] = exact 32-wide tree sum of chunk b ----
    for (int b = wid; b < NCH; b += NW) {
        int p = b * 32 + lane;
        float x = (p == 0) ? 0.0f
                : __fadd_rn(f0, __fmul_rn(__fmul_rn(e[p - 1], am), f0));
        float v = x;
        v = __fadd_rn(v, __shfl_xor_sync(0xffffffffu, v, 1));
        v = __fadd_rn(v, __shfl_xor_sync(0xffffffffu, v, 2));
        v = __fadd_rn(v, __shfl_xor_sync(0xffffffffu, v, 4));
        v = __fadd_rn(v, __shfl_xor_sync(0xffffffffu, v, 8));
        v = __fadd_rn(v, __shfl_xor_sync(0xffffffffu, v, 16));
        if (lane == 0) lev[b] = v;           // LOFF(5) == 0
    }
    __syncthreads();

    // ---- Phase A2: L6..L16 ----
    #pragma unroll 1
    for (int k = 6; k <= 16; ++k) {
        const int n = NSAMP >> k;
        const int src = LOFF(k - 1), dst = LOFF(k);
        for (int i = tid; i < n; i += BS)
            lev[dst + i] = __fadd_rn(lev[src + 2 * i], lev[src + 2 * i + 1]);
        __syncthreads();
    }

    // ---- Phase A3: coarse prefixes P[b] = fold of nodes of count 32b ----
    for (int b = tid; b <= NCH; b += BS) {
        const unsigned cc = (unsigned)b * 32u;
        float s = 0.0f;
        #pragma unroll
        for (int k = 16; k >= 5; --k) {
            if (cc & (1u << k)) {
                unsigned idx = (cc & ~((2u << k) - 1u)) >> k;
                s = __fadd_rn(s, lev[LOFF(k) + idx]);
            }
        }
        P[b] = s;
    }
    __syncthreads();

    // ---- Phase B: emit (no barriers) ----
    for (int b = wid; b < NCH; b += NW) {
        int p = b * 32 + lane;
        float x = (p == 0) ? 0.0f
                : __fadd_rn(f0, __fmul_rn(__fmul_rn(e[p - 1], am), f0));
        float v0 = x;
        float v1 = __fadd_rn(v0, __shfl_xor_sync(0xffffffffu, v0, 1));
        float v2 = __fadd_rn(v1, __shfl_xor_sync(0xffffffffu, v1, 2));
        float v3 = __fadd_rn(v2, __shfl_xor_sync(0xffffffffu, v2, 4));
        float v4 = __fadd_rn(v3, __shfl_xor_sync(0xffffffffu, v3, 8));

        const unsigned m = (unsigned)(lane + 1) & 31u;   // fine bits of count
        float s = (lane == 31) ? P[b + 1] : P[b];

        // fine fold, bits 4..0; after k butterflies lane j holds L_k[local j>>k]
        {
            float t;
            t = __shfl_sync(0xffffffffu, v4, (int)(m & ~31u));
            if (m & 16u) s = __fadd_rn(s, t);
            t = __shfl_sync(0xffffffffu, v3, (int)(m & ~15u));
            if (m & 8u)  s = __fadd_rn(s, t);
            t = __shfl_sync(0xffffffffu, v2, (int)(m & ~7u));
            if (m & 4u)  s = __fadd_rn(s, t);
            t = __shfl_sync(0xffffffffu, v1, (int)(m & ~3u));
            if (m & 2u)  s = __fadd_rn(s, t);
            t = __shfl_sync(0xffffffffu, v0, (int)(m & ~1u));
            if (m & 1u)  s = __fadd_rn(s, t);
        }
        o[p] = sinf(s);
    }
}

extern "C" void kernel_launch(void* const* d_in, const int* in_sizes, int n_in,
                              void* d_out, int out_size)
{
    int im = 0;
    for (int i = 1; i < n_in; ++i)
        if (in_sizes[i] > in_sizes[im]) im = i;
    const int B = in_sizes[im] / NSAMP;

    const float* freqp = nullptr;
    const float* amtp  = nullptr;
    for (int i = 0; i < n_in; ++i) {
        if (i == im) continue;
        if (in_sizes[i] == B) {
            if (!freqp) freqp = (const float*)d_in[i];
            else if (!amtp) amtp = (const float*)d_in[i];
        }
    }
    const float* envp = (const float*)d_in[im];

    osc_kernel<<<B, BS>>>(freqp, envp, amtp, (float*)d_out);
}

// round 4
// speedup vs baseline: 1.7825x; 1.7825x over previous
#include <cuda_runtime.h>
#include <math.h>

// SinusoidalOscillator: out[b,n] = sin(S0[n]), S0 = f32 scan of padded x
// (x[0]=0, x[j]=f0+(env[j-1]*am)*f0) with jax lax.associative_scan's tree.
// Bit-exact closed form (validated: rel_err identical across two schedules):
//   S0[n] = left-assoc fold, coarsest->finest, of binary-decomposition tree
//   nodes of count c=n+1. Per-thread serial version: thread owns 32 samples,
//   computes local tree nodes in registers, folds coarse bits from smem lev.

#define NSAMP  65536
#define BS     256
#define TILE   (BS * 32)        // 8192 samples per tile
#define NT     (NSAMP / TILE)   // 8
#define PADW   33               // padded smem row stride (conflict-free)

// L5..L16 packed in lev[4096]: LOFF(k) = 4096 - (NSAMP >> (k-1))
#define LOFF(k) (4096 - (NSAMP >> ((k) - 1)))

#define XS_FLOATS (BS * PADW)             // 8448
#define SMEM_BYTES ((XS_FLOATS + 4096) * 4)

__device__ __forceinline__ float coarse_fold(const float* __restrict__ lev, unsigned c)
{
    float s = 0.0f;
    #pragma unroll
    for (int k = 16; k >= 5; --k) {
        if (c & (1u << k)) {
            unsigned idx = (c & ~((2u << k) - 1u)) >> k;
            s = __fadd_rn(s, lev[LOFF(k) + idx]);
        }
    }
    return s;
}

__global__ __launch_bounds__(BS, 4)
void osc_kernel(const float* __restrict__ freq,
                const float* __restrict__ env,
                const float* __restrict__ moda,
                float* __restrict__ out)
{
    extern __shared__ float sm[];
    float* xs  = sm;                 // staged tile, padded: slot(j) = (j>>5)*33 + (j&31)
    float* lev = sm + XS_FLOATS;     // L5..L16

    const int row = blockIdx.x;
    const int tid = threadIdx.x;

    const float f0hz = __fadd_rn(20.0f, __fmul_rn(1980.0f, freq[row]));
    const float f0   = __fdiv_rn(__fmul_rn(f0hz, 6.28318530717958647692f), 48000.0f);
    const float am   = __fadd_rn(-1.0f, __fmul_rn(3.0f, moda[row]));

    const float* e = env + (size_t)row * NSAMP;
    float*       o = out + (size_t)row * NSAMP;

    // ---------------- Phase A: L5[b] = exact 32-wide tree sum per chunk ----------------
    for (int t = 0; t < NT; ++t) {
        const int T0 = t * TILE;
        // slot j holds e[T0 + j - 1]; aligned coalesced loads of e[T0 + j]
        for (int j = tid; j < TILE - 1; j += BS) {
            float v = e[T0 + j];
            int sl = j + 1;
            xs[(sl >> 5) * PADW + (sl & 31)] = v;
        }
        if (tid == 0) xs[0] = (T0 == 0) ? 0.0f : e[T0 - 1];
        __syncthreads();

        const int qoff = tid * PADW;
        const int b    = t * BS + tid;
        float t1[16];
        #pragma unroll
        for (int i = 0; i < 16; ++i) {
            float ea = xs[qoff + 2 * i], eb = xs[qoff + 2 * i + 1];
            float xa = __fadd_rn(f0, __fmul_rn(__fmul_rn(ea, am), f0));
            float xb = __fadd_rn(f0, __fmul_rn(__fmul_rn(eb, am), f0));
            if (b == 0 && i == 0) xa = 0.0f;        // global x[0] = 0
            t1[i] = __fadd_rn(xa, xb);
        }
        float t2[8];
        #pragma unroll
        for (int i = 0; i < 8; ++i) t2[i] = __fadd_rn(t1[2 * i], t1[2 * i + 1]);
        float t3[4];
        #pragma unroll
        for (int i = 0; i < 4; ++i) t3[i] = __fadd_rn(t2[2 * i], t2[2 * i + 1]);
        float t4a = __fadd_rn(t3[0], t3[1]);
        float t4b = __fadd_rn(t3[2], t3[3]);
        lev[b] = __fadd_rn(t4a, t4b);               // LOFF(5) == 0
        __syncthreads();
    }

    // ---------------- L6..L16 ----------------
    #pragma unroll 1
    for (int k = 6; k <= 16; ++k) {
        const int n = NSAMP >> k;
        const int src = LOFF(k - 1), dst = LOFF(k);
        for (int i = tid; i < n; i += BS)
            lev[dst + i] = __fadd_rn(lev[src + 2 * i], lev[src + 2 * i + 1]);
        __syncthreads();
    }

    // ---------------- Phase B: per-thread emit, barrier-free inner math ----------------
    for (int t = 0; t < NT; ++t) {
        const int T0 = t * TILE;
        for (int j = tid; j < TILE - 1; j += BS) {
            float v = e[T0 + j];
            int sl = j + 1;
            xs[(sl >> 5) * PADW + (sl & 31)] = v;
        }
        if (tid == 0) xs[0] = (T0 == 0) ? 0.0f : e[T0 - 1];
        __syncthreads();

        const int qoff = tid * PADW;
        const int b    = t * BS + tid;
        const unsigned cc = (unsigned)b * 32u;

        const float s0 = coarse_fold(lev, cc);
        const float s1 = coarse_fold(lev, cc + 32u);

        // local tree nodes (registers only)
        float xe[16], t1[16];
        #pragma unroll
        for (int i = 0; i < 16; ++i) {
            float ea = xs[qoff + 2 * i], eb = xs[qoff + 2 * i + 1];
            float xa = __fadd_rn(f0, __fmul_rn(__fmul_rn(ea, am), f0));
            float xb = __fadd_rn(f0, __fmul_rn(__fmul_rn(eb, am), f0));
            if (b == 0 && i == 0) xa = 0.0f;
            xe[i] = xa;
            t1[i] = __fadd_rn(xa, xb);
        }
        float t2[8];
        #pragma unroll
        for (int i = 0; i < 8; ++i) t2[i] = __fadd_rn(t1[2 * i], t1[2 * i + 1]);
        float t3[4];
        #pragma unroll
        for (int i = 0; i < 4; ++i) t3[i] = __fadd_rn(t2[2 * i], t2[2 * i + 1]);
        const float t4_0 = __fadd_rn(t3[0], t3[1]);

        // emit m = 1..32 (count c = 32b + m); slice is private -> overwrite in place
        #pragma unroll
        for (int m = 1; m <= 32; ++m) {
            float s;
            if (m == 32) {
                s = s1;                              // pure coarse fold of 32(b+1)
            } else {
                s = s0;
                if (m & 16) s = __fadd_rn(s, t4_0);
                if (m & 8)  s = __fadd_rn(s, t3[(m & 16) ? 2 : 0]);
                if (m & 4)  s = __fadd_rn(s, t2[(m & ~7) >> 2]);
                if (m & 2)  s = __fadd_rn(s, t1[(m & ~3) >> 1]);
                if (m & 1)  s = __fadd_rn(s, xe[(m & ~1) >> 1]);
            }
            xs[qoff + (m - 1)] = sinf(s);
        }
        __syncthreads();

        for (int j = tid; j < TILE; j += BS)
            o[T0 + j] = xs[(j >> 5) * PADW + (j & 31)];
        __syncthreads();
    }
}

extern "C" void kernel_launch(void* const* d_in, const int* in_sizes, int n_in,
                              void* d_out, int out_size)
{
    int im = 0;
    for (int i = 1; i < n_in; ++i)
        if (in_sizes[i] > in_sizes[im]) im = i;
    const int B = in_sizes[im] / NSAMP;

    const float* freqp = nullptr;
    const float* amtp  = nullptr;
    for (int i = 0; i < n_in; ++i) {
        if (i == im) continue;
        if (in_sizes[i] == B) {
            if (!freqp) freqp = (const float*)d_in[i];
            else if (!amtp) amtp = (const float*)d_in[i];
        }
    }
    const float* envp = (const float*)d_in[im];

    cudaFuncSetAttribute(osc_kernel, cudaFuncAttributeMaxDynamicSharedMemorySize,
                         SMEM_BYTES);
    osc_kernel<<<B, BS, SMEM_BYTES>>>(freqp, envp, amtp, (float*)d_out);
}

// round 13
// speedup vs baseline: 1.8144x; 1.0179x over previous
#include <cuda_runtime.h>
#include <math.h>

// SinusoidalOscillator: out[b,n] = sin(S0[n]), S0 = f32 scan of padded x
// (x[0]=0, x[j]=f0+(env[j-1]*am)*f0) with jax lax.associative_scan's tree.
// Validated bit-exact closed form: S0[n] = left-assoc fold, coarsest->finest,
// of binary-decomposition tree nodes of count c=n+1.
// Two-kernel split: K1 computes L5 (32-wide tree sums) barrier-free;
// K2 rebuilds L6..L16 per row in smem and emits.

#define NSAMP  65536
#define BS     256
#define SEGS   8                       // CTAs per row
#define CHPS   (NSAMP / 32)            // 2048 L5 chunks per row
#define MAXB   1024

// L5..L16 packed in lev[4096]: LOFF(k) = 4096 - (NSAMP >> (k-1)); LOFF(5)=0
#define LOFF(k) (4096 - (NSAMP >> ((k) - 1)))
#define PADW   33
#define XS_FLOATS (BS * PADW)          // 8448
#define SMEM_BYTES ((XS_FLOATS + 4096) * 4)

__device__ float g_lev5[MAXB * CHPS];  // 8 MB scratch

#define XFORM(ev) __fadd_rn(f0, __fmul_rn(__fmul_rn((ev), am), f0))

__device__ __forceinline__ float coarse_fold(const float* __restrict__ lev, unsigned c)
{
    float s = 0.0f;
    #pragma unroll
    for (int k = 16; k >= 5; --k) {
        if (c & (1u << k)) {
            unsigned idx = (c & ~((2u << k) - 1u)) >> k;
            s = __fadd_rn(s, lev[LOFF(k) + idx]);
        }
    }
    return s;
}

// ---------------- K1: per-chunk 32-wide tree sums -> g_lev5 ----------------
__global__ __launch_bounds__(BS)
void k_reduce(const float* __restrict__ freq,
              const float* __restrict__ env,
              const float* __restrict__ moda)
{
    const int row = blockIdx.x >> 3;
    const int seg = blockIdx.x & 7;
    const int b   = seg * BS + threadIdx.x;      // row-local chunk 0..2047
    const int p0  = b * 32;

    const float f0hz = __fadd_rn(20.0f, __fmul_rn(1980.0f, freq[row]));
    const float f0   = __fdiv_rn(__fmul_rn(f0hz, 6.28318530717958647692f), 48000.0f);
    const float am   = __fadd_rn(-1.0f, __fmul_rn(3.0f, moda[row]));

    const float* e = env + (size_t)row * NSAMP;
    const float4* ep = (const float4*)(e + p0);

    float pe = (b == 0) ? 0.0f : e[p0 - 1];
    float t1[16];
    #pragma unroll
    for (int g = 0; g < 8; ++g) {
        float4 v = ep[g];
        float x0 = XFORM(pe);
        float x1 = XFORM(v.x);
        float x2 = XFORM(v.y);
        float x3 = XFORM(v.z);
        if (b == 0 && g == 0) x0 = 0.0f;         // global pad x[0] = 0
        t1[2 * g]     = __fadd_rn(x0, x1);
        t1[2 * g + 1] = __fadd_rn(x2, x3);
        pe = v.w;
    }
    float t2[8];
    #pragma unroll
    for (int i = 0; i < 8; ++i) t2[i] = __fadd_rn(t1[2 * i], t1[2 * i + 1]);
    float t3[4];
    #pragma unroll
    for (int i = 0; i < 4; ++i) t3[i] = __fadd_rn(t2[2 * i], t2[2 * i + 1]);
    float a = __fadd_rn(t3[0], t3[1]);
    float c = __fadd_rn(t3[2], t3[3]);
    g_lev5[(size_t)row * CHPS + b] = __fadd_rn(a, c);
}

// ---------------- K2: build L6..L16, fold, emit sin ----------------
__global__ __launch_bounds__(BS, 4)
void k_emit(const float* __restrict__ freq,
            const float* __restrict__ env,
            const float* __restrict__ moda,
            float* __restrict__ out)
{
    extern __shared__ float sm[];
    float* lev = sm;                  // 4096: L5..L16
    float* xs  = sm + 4096;           // padded output bounce

    const int row = blockIdx.x >> 3;
    const int seg = blockIdx.x & 7;
    const int tid = threadIdx.x;

    // load row L5 (2048 floats) -> lev[0..2047]
    {
        const float4* lp = (const float4*)(g_lev5 + (size_t)row * CHPS);
        float4* dp = (float4*)lev;
        #pragma unroll
        for (int i = 0; i < 2; ++i)
            dp[tid + i * BS] = lp[tid + i * BS];
    }
    __syncthreads();

    // L6..L16
    #pragma unroll 1
    for (int k = 6; k <= 16; ++k) {
        const int n = NSAMP >> k;
        const int src = LOFF(k - 1), dst = LOFF(k);
        for (int i = tid; i < n; i += BS)
            lev[dst + i] = __fadd_rn(lev[src + 2 * i], lev[src + 2 * i + 1]);
        __syncthreads();
    }

    const float f0hz = __fadd_rn(20.0f, __fmul_rn(1980.0f, freq[row]));
    const float f0   = __fdiv_rn(__fmul_rn(f0hz, 6.28318530717958647692f), 48000.0f);
    const float am   = __fadd_rn(-1.0f, __fmul_rn(3.0f, moda[row]));

    const float* e = env + (size_t)row * NSAMP;
    float*       o = out + (size_t)row * NSAMP;

    const int b  = seg * BS + tid;               // row-local chunk
    const int p0 = b * 32;
    const unsigned cc = (unsigned)b * 32u;

    const float s0 = coarse_fold(lev, cc);
    const float s1 = coarse_fold(lev, cc + 32u);

    // local tree nodes from direct vector loads
    const float4* ep = (const float4*)(e + p0);
    float pe = (b == 0) ? 0.0f : e[p0 - 1];
    float xe[16], t1[16];
    #pragma unroll
    for (int g = 0; g < 8; ++g) {
        float4 v = ep[g];
        float x0 = XFORM(pe);
        float x1 = XFORM(v.x);
        float x2 = XFORM(v.y);
        float x3 = XFORM(v.z);
        if (b == 0 && g == 0) x0 = 0.0f;
        xe[2 * g]     = x0;
        xe[2 * g + 1] = x2;
        t1[2 * g]     = __fadd_rn(x0, x1);
        t1[2 * g + 1] = __fadd_rn(x2, x3);
        pe = v.w;
    }
    float t2[8];
    #pragma unroll
    for (int i = 0; i < 8; ++i) t2[i] = __fadd_rn(t1[2 * i], t1[2 * i + 1]);
    float t3[4];
    #pragma unroll
    for (int i = 0; i < 4; ++i) t3[i] = __fadd_rn(t2[2 * i], t2[2 * i + 1]);
    const float t4_0 = __fadd_rn(t3[0], t3[1]);

    const int qoff = tid * PADW;
    #pragma unroll
    for (int m = 1; m <= 32; ++m) {
        float s;
        if (m == 32) {
            s = s1;
        } else {
            s = s0;
            if (m & 16) s = __fadd_rn(s, t4_0);
            if (m & 8)  s = __fadd_rn(s, t3[(m & 16) ? 2 : 0]);
            if (m & 4)  s = __fadd_rn(s, t2[(m & ~7) >> 2]);
            if (m & 2)  s = __fadd_rn(s, t1[(m & ~3) >> 1]);
            if (m & 1)  s = __fadd_rn(s, xe[(m & ~1) >> 1]);
        }
        xs[qoff + (m - 1)] = sinf(s);
    }
    __syncthreads();

    const int T0 = seg * (BS * 32);
    #pragma unroll 4
    for (int j = tid; j < BS * 32; j += BS)
        o[T0 + j] = xs[(j >> 5) * PADW + (j & 31)];
}

extern "C" void kernel_launch(void* const* d_in, const int* in_sizes, int n_in,
                              void* d_out, int out_size)
{
    int im = 0;
    for (int i = 1; i < n_in; ++i)
        if (in_sizes[i] > in_sizes[im]) im = i;
    const int B = in_sizes[im] / NSAMP;

    const float* freqp = nullptr;
    const float* amtp  = nullptr;
    for (int i = 0; i < n_in; ++i) {
        if (i == im) continue;
        if (in_sizes[i] == B) {
            if (!freqp) freqp = (const float*)d_in[i];
            else if (!amtp) amtp = (const float*)d_in[i];
        }
    }
    const float* envp = (const float*)d_in[im];

    cudaFuncSetAttribute(k_emit, cudaFuncAttributeMaxDynamicSharedMemorySize,
                         SMEM_BYTES);
    k_reduce<<<B * SEGS, BS>>>(freqp, envp, amtp);
    k_emit<<<B * SEGS, BS, SMEM_BYTES>>>(freqp, envp, amtp, (float*)d_out);
}

// round 14
// speedup vs baseline: 2.0568x; 1.1336x over previous
#include <cuda_runtime.h>
#include <math.h>

// SinusoidalOscillator: out[b,n] = sin(S0[n]), S0 = f32 scan of padded x
// (x[0]=0, x[j]=f0+(env[j-1]*am)*f0), bit-matching jax lax.associative_scan.
// S0[n] = left-assoc fold, coarsest->finest, of binary-decomposition tree
// nodes of count c=n+1 (validated bit-exact, rel_err 7.356e-4 across schedules).
// K1: 32-wide tree sums (L5) barrier-free -> scratch.
// K2: rebuild L6..L16 in smem; per-thread 2x16-sample halves (register nodes),
//     vectorized smem bounce for coalesced stores; launch_bounds(256,5).

#define NSAMP  65536
#define BS     256
#define SEGS   8
#define CHPS   (NSAMP / 32)
#define MAXB   1024

#define LOFF(k) (4096 - (NSAMP >> ((k) - 1)))
#define PADW   20                      // floats per thread slot (16 data + 4 pad)

__device__ float g_lev5[MAXB * CHPS];  // 8 MB scratch

__device__ __forceinline__ float xf(float ev, float f0, float am)
{
    return __fadd_rn(f0, __fmul_rn(__fmul_rn(ev, am), f0));
}

__device__ __forceinline__ float coarse_fold(const float* __restrict__ lev, unsigned c)
{
    float s = 0.0f;
    #pragma unroll
    for (int k = 16; k >= 5; --k) {
        if (c & (1u << k)) {
            unsigned idx = (c & ~((2u << k) - 1u)) >> k;
            s = __fadd_rn(s, lev[LOFF(k) + idx]);
        }
    }
    return s;
}

// nodes for 16 consecutive samples: xe[i]=x[2i], t1=pairs, t2=quads, t3=eights
__device__ __forceinline__ void nodes16(const float4* __restrict__ ep4,
                                        float pe_in, bool zero_first,
                                        float f0, float am,
                                        float* xe, float* t1, float* t2, float* t3,
                                        float& pe_out)
{
    float pe = pe_in;
    #pragma unroll
    for (int g = 0; g < 4; ++g) {
        float4 v = ep4[g];
        float x0 = xf(pe,  f0, am);
        float x1 = xf(v.x, f0, am);
        float x2 = xf(v.y, f0, am);
        float x3 = xf(v.z, f0, am);
        if (zero_first && g == 0) x0 = 0.0f;
        xe[2 * g]     = x0;
        xe[2 * g + 1] = x2;
        t1[2 * g]     = __fadd_rn(x0, x1);
        t1[2 * g + 1] = __fadd_rn(x2, x3);
        pe = v.w;
    }
    #pragma unroll
    for (int i = 0; i < 4; ++i) t2[i] = __fadd_rn(t1[2 * i], t1[2 * i + 1]);
    t3[0] = __fadd_rn(t2[0], t2[1]);
    t3[1] = __fadd_rn(t2[2], t2[3]);
    pe_out = pe;
}

// emit 16 sins: local counts mm=1..15 fold from sbase; mm=16 uses stop.
__device__ __forceinline__ void emit16(float sbase, float stop,
                                       const float* xe, const float* t1,
                                       const float* t2, const float* t3,
                                       float* __restrict__ dst)
{
    float4 r;
    #pragma unroll
    for (int mm = 1; mm <= 16; ++mm) {
        float s;
        if (mm == 16) {
            s = stop;
        } else {
            s = sbase;
            if (mm & 8) s = __fadd_rn(s, t3[0]);
            if (mm & 4) s = __fadd_rn(s, t2[(mm & ~7) >> 2]);
            if (mm & 2) s = __fadd_rn(s, t1[(mm & ~3) >> 1]);
            if (mm & 1) s = __fadd_rn(s, xe[(mm & ~1) >> 1]);
        }
        (&r.x)[(mm - 1) & 3] = sinf(s);
        if ((mm & 3) == 0)
            ((float4*)dst)[(mm >> 2) - 1] = r;
    }
}

// ---------------- K1: per-chunk 32-wide tree sums -> g_lev5 ----------------
__global__ __launch_bounds__(BS)
void k_reduce(const float* __restrict__ freq,
              const float* __restrict__ env,
              const float* __restrict__ moda)
{
    const int row = blockIdx.x >> 3;
    const int seg = blockIdx.x & 7;
    const int b   = seg * BS + threadIdx.x;
    const int p0  = b * 32;

    const float f0hz = __fadd_rn(20.0f, __fmul_rn(1980.0f, freq[row]));
    const float f0   = __fdiv_rn(__fmul_rn(f0hz, 6.28318530717958647692f), 48000.0f);
    const float am   = __fadd_rn(-1.0f, __fmul_rn(3.0f, moda[row]));

    const float* e = env + (size_t)row * NSAMP;
    const float4* ep = (const float4*)(e + p0);

    float pe = (b == 0) ? 0.0f : e[p0 - 1];
    float t1[16];
    #pragma unroll
    for (int g = 0; g < 8; ++g) {
        float4 v = ep[g];
        float x0 = xf(pe,  f0, am);
        float x1 = xf(v.x, f0, am);
        float x2 = xf(v.y, f0, am);
        float x3 = xf(v.z, f0, am);
        if (b == 0 && g == 0) x0 = 0.0f;
        t1[2 * g]     = __fadd_rn(x0, x1);
        t1[2 * g + 1] = __fadd_rn(x2, x3);
        pe = v.w;
    }
    float t2[8];
    #pragma unroll
    for (int i = 0; i < 8; ++i) t2[i] = __fadd_rn(t1[2 * i], t1[2 * i + 1]);
    float t3[4];
    #pragma unroll
    for (int i = 0; i < 4; ++i) t3[i] = __fadd_rn(t2[2 * i], t2[2 * i + 1]);
    float a = __fadd_rn(t3[0], t3[1]);
    float c = __fadd_rn(t3[2], t3[3]);
    g_lev5[(size_t)row * CHPS + b] = __fadd_rn(a, c);
}

// ---------------- K2: build L6..L16, fold, emit sin ----------------
__global__ __launch_bounds__(BS, 5)
void k_emit(const float* __restrict__ freq,
            const float* __restrict__ env,
            const float* __restrict__ moda,
            float* __restrict__ out)
{
    __shared__ float lev[4096];        // L5..L16
    __shared__ float xs[BS * PADW];    // half-chunk sin bounce (5120 floats)

    const int row = blockIdx.x >> 3;
    const int seg = blockIdx.x & 7;
    const int tid = threadIdx.x;

    // load row L5 (2048 floats)
    {
        const float4* lp = (const float4*)(g_lev5 + (size_t)row * CHPS);
        float4* dp = (float4*)lev;
        #pragma unroll
        for (int i = 0; i < 2; ++i)
            dp[tid + i * BS] = lp[tid + i * BS];
    }
    __syncthreads();

    // L6..L16
    #pragma unroll 1
    for (int k = 6; k <= 16; ++k) {
        const int n = NSAMP >> k;
        const int src = LOFF(k - 1), dst = LOFF(k);
        for (int i = tid; i < n; i += BS)
            lev[dst + i] = __fadd_rn(lev[src + 2 * i], lev[src + 2 * i + 1]);
        __syncthreads();
    }

    const float f0hz = __fadd_rn(20.0f, __fmul_rn(1980.0f, freq[row]));
    const float f0   = __fdiv_rn(__fmul_rn(f0hz, 6.28318530717958647692f), 48000.0f);
    const float am   = __fadd_rn(-1.0f, __fmul_rn(3.0f, moda[row]));

    const float* e = env + (size_t)row * NSAMP;
    float*       o = out + (size_t)row * NSAMP;

    const int b  = seg * BS + tid;
    const int p0 = b * 32;
    const unsigned cc = (unsigned)b * 32u;
    const int T0 = seg * (BS * 32);
    const int qoff = tid * PADW;

    const float s0 = coarse_fold(lev, cc);
    const float s1 = coarse_fold(lev, cc + 32u);

    const float4* ep = (const float4*)(e + p0);
    float xe[8], t1[8], t2[4], t3[2];
    float pe = (b == 0) ? 0.0f : e[p0 - 1];

    // ---- half 0: samples [p0, p0+16) ----
    nodes16(ep, pe, b == 0, f0, am, xe, t1, t2, t3, pe);
    const float t4_0 = __fadd_rn(t3[0], t3[1]);
    emit16(s0, __fadd_rn(s0, t4_0), xe, t1, t2, t3, xs + qoff);
    __syncthreads();
    #pragma unroll
    for (int q = 0; q < 4; ++q) {
        int v  = tid + q * BS;
        int t  = v >> 2, qq = v & 3;
        float4 val = ((const float4*)(xs + t * PADW))[qq];
        ((float4*)(o + T0 + t * 32))[qq] = val;
    }
    __syncthreads();

    // ---- half 1: samples [p0+16, p0+32) ----
    nodes16(ep + 4, pe, false, f0, am, xe, t1, t2, t3, pe);
    emit16(__fadd_rn(s0, t4_0), s1, xe, t1, t2, t3, xs + qoff);
    __syncthreads();
    #pragma unroll
    for (int q = 0; q < 4; ++q) {
        int v  = tid + q * BS;
        int t  = v >> 2, qq = v & 3;
        float4 val = ((const float4*)(xs + t * PADW))[qq];
        ((float4*)(o + T0 + t * 32 + 16))[qq] = val;
    }
}

extern "C" void kernel_launch(void* const* d_in, const int* in_sizes, int n_in,
                              void* d_out, int out_size)
{
    int im = 0;
    for (int i = 1; i < n_in; ++i)
        if (in_sizes[i] > in_sizes[im]) im = i;
    const int B = in_sizes[im] / NSAMP;

    const float* freqp = nullptr;
    const float* amtp  = nullptr;
    for (int i = 0; i < n_in; ++i) {
        if (i == im) continue;
        if (in_sizes[i] == B) {
            if (!freqp) freqp = (const float*)d_in[i];
            else if (!amtp) amtp = (const float*)d_in[i];
        }
    }
    const float* envp = (const float*)d_in[im];

    k_reduce<<<B * SEGS, BS>>>(freqp, envp, amtp);
    k_emit<<<B * SEGS, BS>>>(freqp, envp, amtp, (float*)d_out);
}